// round 8
// baseline (speedup 1.0000x reference)
#include <cuda_runtime.h>
#include <cstdint>
#include <math.h>

#define B_    32
#define C_    128
#define O_    256
#define HWD   32
#define L_    1024
#define CKK   1152
#define S_    9
#define SUBK  128
#define BOL   8388608       // B*O*L  (s-stride in y)
#define OLl   262144        // O*L    (b-stride in y)

// ---------------- device scratch ----------------
__device__ __align__(16) int8_t  g_qi[B_*C_*HWD*HWD];
__device__ __align__(16) int8_t  g_qw[O_*CKK];
__device__ __align__(16) int8_t  g_qa[(size_t)B_*L_*CKK];
__device__ __align__(16) short   g_y[(size_t)S_*BOL];
__device__ float g_A[S_*O_];   // inv_std*gamma/3
__device__ float g_Bc[S_*O_];  // beta - mean*inv_std*gamma

// ---------------- compile-time threefry keys ----------------
constexpr uint32_t crotl(uint32_t x, int r){ return (x << r) | (x >> (32 - r)); }
struct KP { uint32_t a, b; };
constexpr KP host_tf(uint32_t k0, uint32_t k1, uint32_t x0, uint32_t x1){
  uint32_t ks2 = k0 ^ k1 ^ 0x1BD11BDAu;
  x0 += k0; x1 += k1;
  const int RA[4] = {13,15,26,6};
  const int RB[4] = {17,29,16,24};
  const uint32_t ka[5] = {k1, ks2, k0, k1, ks2};
  const uint32_t kb[5] = {ks2, k0, k1, ks2, k0};
  for (int blk = 0; blk < 5; blk++){
    const int* R = (blk & 1) ? RB : RA;
    for (int i = 0; i < 4; i++){ x0 += x1; x1 = crotl(x1, R[i]); x1 ^= x0; }
    x0 += ka[blk]; x1 += kb[blk] + (uint32_t)(blk + 1);
  }
  return KP{x0, x1};
}
// fold_in(key(42), t) = threefry2x32(key=[0,42], data=[0,t])
constexpr KP KEY0 = host_tf(0u, 42u, 0u, 0u);
constexpr KP KEY1 = host_tf(0u, 42u, 0u, 1u);
constexpr KP KEY2 = host_tf(0u, 42u, 0u, 2u);
constexpr KP KEY3 = host_tf(0u, 42u, 0u, 3u);

// rotate on alu pipe (SHF):
#define TF_R(r)  { x0 += x1; x1 = __funnelshift_l(x1, x1, (r)); x1 ^= x0; }
// rotate on fma pipe: (x<<r) and (x>>(32-r)) have disjoint bits -> OR == ADD,
// expressed as IMAD pair (x * 2^r  +  umulhi(x, 2^r)). Plain adds elsewhere so
// ptxas keeps its IADD3 3-input fusion + IMAD alternation.
#define TF_RM(r) { x0 += x1; \
  x1 = (x1 * (1u << (r))) + __umulhi(x1, 1u << (r)); x1 ^= x0; }

template<uint32_t K0, uint32_t K1>
__device__ __forceinline__ uint32_t tf_bits(uint32_t ctr){
  constexpr uint32_t KS2 = K0 ^ K1 ^ 0x1BD11BDAu;
  uint32_t x0 = K0;            // ctr_hi = 0
  uint32_t x1 = ctr + K1;
  TF_RM(13) TF_RM(15) TF_RM(26) TF_R(6)
  x0 += K1;  x1 += KS2 + 1u;
  TF_RM(17) TF_RM(29) TF_RM(16) TF_R(24)
  x0 += KS2; x1 += K0 + 2u;
  TF_RM(13) TF_RM(15) TF_RM(26) TF_R(6)
  x0 += K0;  x1 += K1 + 3u;
  TF_RM(17) TF_RM(29) TF_RM(16) TF_R(24)
  x0 += K1;  x1 += KS2 + 4u;
  TF_RM(13) TF_RM(15) TF_R(26) TF_R(6)
  x0 += KS2; x1 += K0 + 5u;
  return x0 ^ x1;              // partitionable: out = w0 ^ w1
}

// ---------------- k1: quantize input ----------------
__global__ void k_quant_input(const float* __restrict__ in, int n){
  int i = blockIdx.x * 256 + threadIdx.x;
  if (i < n){
    float v = fminf(fmaxf(in[i], -1.0f), 1.0f);
    g_qi[i] = (int8_t)__float2int_rn(v * 3.0f);
  }
}

// ---------------- k2: weight sign ----------------
__global__ void k_qw(const float* __restrict__ w){
  int o = blockIdx.x, t = threadIdx.x;
  const float* wr = w + (size_t)o * CKK;
  double s = 0.0;
  for (int i = t; i < CKK; i += 128) s += (double)wr[i];
  __shared__ double sh[128];
  sh[t] = s; __syncthreads();
  for (int d = 64; d; d >>= 1){ if (t < d) sh[t] += sh[t + d]; __syncthreads(); }
  float m = (float)(sh[0] / (double)CKK);
  for (int i = t; i < CKK; i += 128){
    float d = wr[i] - m;
    g_qw[(size_t)o * CKK + i] = (int8_t)((d > 0.0f) - (d < 0.0f));
  }
}

// ---------------- k3: im2col [b][l][ckk], ckk = c*9 + dy*3 + dx ----------------
__global__ void k_im2col(){
  int bid = blockIdx.x;
  int b = bid >> 5, y0 = bid & 31;
  int t = threadIdx.x;
  __shared__ int8_t sq[C_ * 3 * HWD];
  for (int i = t; i < C_ * 3 * HWD; i += 256){
    int c = i / 96, rr = (i % 96) >> 5, x = i & 31;
    int yy = y0 + rr - 1;
    sq[i] = (yy >= 0 && yy < HWD) ? g_qi[((size_t)(b * C_ + c) * HWD + yy) * HWD + x] : (int8_t)0;
  }
  __syncthreads();
  int8_t* dst = g_qa + (size_t)(b * L_ + y0 * HWD) * CKK;
  for (int idx = t; idx < HWD * CKK; idx += 256){
    int x0 = idx / CKK, ck = idx - x0 * CKK;
    int c = ck / 9, j = ck - c * 9;
    int dy = j / 3, dx = j - dy * 3;
    int xx = x0 + dx - 1;
    int8_t v = 0;
    if (xx >= 0 && xx < HWD) v = sq[(c * 3 + dy) * HWD + xx];
    dst[idx] = v;
  }
}

// ---------------- k4: per-subarray int8 GEMM (dp4a), 128l x 64o tile ----------------
__global__ void __launch_bounds__(256) k_gemm(){
  int l0 = blockIdx.x * 128, o0 = blockIdx.y * 64;
  int sb = blockIdx.z, s = sb >> 5, b = sb & 31;
  __shared__ __align__(16) int8_t sA[128][144];
  __shared__ __align__(16) int8_t sW[64][144];
  int t = threadIdx.x;
  const int8_t* gA = g_qa + (size_t)(b * L_ + l0) * CKK + s * SUBK;
  const int8_t* gW = g_qw + (size_t)o0 * CKK + s * SUBK;
  #pragma unroll
  for (int m = t; m < 1024; m += 256){
    int row = m >> 3, c16 = (m & 7) * 16;
    *(int4*)&sA[row][c16] = *(const int4*)(gA + (size_t)row * CKK + c16);
  }
  #pragma unroll
  for (int m = t; m < 512; m += 256){
    int row = m >> 3, c16 = (m & 7) * 16;
    *(int4*)&sW[row][c16] = *(const int4*)(gW + (size_t)row * CKK + c16);
  }
  __syncthreads();
  int tx = t & 15, ty = t >> 4;
  int acc[4][8] = {};
  #pragma unroll
  for (int kc = 0; kc < 8; kc++){
    int4 a4[8], w4[4];
    #pragma unroll
    for (int il = 0; il < 8; il++) a4[il] = *(const int4*)&sA[tx + 16 * il][kc * 16];
    #pragma unroll
    for (int io = 0; io < 4; io++) w4[io] = *(const int4*)&sW[ty + 16 * io][kc * 16];
    #pragma unroll
    for (int io = 0; io < 4; io++)
      #pragma unroll
      for (int il = 0; il < 8; il++){
        acc[io][il] = __dp4a(a4[il].x, w4[io].x, acc[io][il]);
        acc[io][il] = __dp4a(a4[il].y, w4[io].y, acc[io][il]);
        acc[io][il] = __dp4a(a4[il].z, w4[io].z, acc[io][il]);
        acc[io][il] = __dp4a(a4[il].w, w4[io].w, acc[io][il]);
      }
  }
  size_t base = (size_t)s * BOL + (size_t)b * OLl;
  #pragma unroll
  for (int io = 0; io < 4; io++)
    #pragma unroll
    for (int il = 0; il < 8; il++)
      g_y[base + (size_t)(o0 + ty + 16 * io) * 1024 + (l0 + tx + 16 * il)] = (short)acc[io][il];
}

// ---------------- k5: BN stats per (s,o) ----------------
__global__ void k_stats(const float* __restrict__ gamma, const float* __restrict__ beta){
  int so = blockIdx.x;
  int s = so >> 8, o = so & 255;
  int t = threadIdx.x;                  // 128
  const int4* base = (const int4*)(g_y + (size_t)s * BOL + (size_t)o * 1024);
  int sy = 0; unsigned int sy2 = 0;
  #pragma unroll 4
  for (int b = 0; b < B_; b++){
    int4 v = base[(size_t)b * (OLl / 8) + t];
    short vv[8]; *(int4*)vv = v;
    #pragma unroll
    for (int q = 0; q < 8; q++){
      int x = vv[q];
      sy += x; sy2 += (unsigned int)(x * x);
    }
  }
  for (int d = 16; d; d >>= 1){
    sy  += __shfl_down_sync(0xffffffffu, sy, d);
    sy2 += __shfl_down_sync(0xffffffffu, sy2, d);
  }
  __shared__ int ssy[4]; __shared__ unsigned int ssy2[4];
  if ((t & 31) == 0){ ssy[t >> 5] = sy; ssy2[t >> 5] = sy2; }
  __syncthreads();
  if (t == 0){
    long long S1 = 0; unsigned long long S2 = 0;
    #pragma unroll
    for (int w = 0; w < 4; w++){ S1 += ssy[w]; S2 += ssy2[w]; }
    const double N = 32768.0;
    double mean = (double)S1 / (3.0 * N);
    double e2   = (double)S2 / (9.0 * N);
    double var  = e2 - mean * mean;
    double inv  = (double)gamma[o] / sqrt(var + 1e-5);
    g_A[so]  = (float)(inv / 3.0);
    g_Bc[so] = (float)((double)beta[o] - mean * inv);
  }
}

// ---------------- k6: sampling (R4-proven float compare) ----------------
// compare trick: u < p  <=>  (float)(bits>>9) < p*2^23   (all quantities exact in f32)
__global__ void __launch_bounds__(256) k_sample(float* __restrict__ out){
  uint32_t j = blockIdx.x * 256 + threadIdx.x;    // flat (b,o,l)
  int o = (j >> 10) & 255;
  float fcnt = 0.0f;
  #pragma unroll 1
  for (int s = 0; s < S_; s++){
    uint32_t idx = (uint32_t)s * BOL + j;
    float A  = __ldg(&g_A[s * 256 + o]);
    float Bc = __ldg(&g_Bc[s * 256 + o]);
    float zf = fmaf((float)g_y[idx], A, Bc);
    zf = fminf(fmaxf(zf, -1.0f), 1.0f);
    float p = fminf(fmaxf((zf + 1.0f) * 0.5f, 0.0f), 1.0f);
    float p23 = p * 8388608.0f;                   // exact (power-of-2 scale)
    uint32_t b0 = tf_bits<KEY0.a, KEY0.b>(idx);
    uint32_t b1 = tf_bits<KEY1.a, KEY1.b>(idx);
    uint32_t b2 = tf_bits<KEY2.a, KEY2.b>(idx);
    uint32_t b3 = tf_bits<KEY3.a, KEY3.b>(idx);
    float m0 = (float)__umulhi(b0, 8388608u);     // == b0 >> 9, off the alu pipe
    float m1 = (float)__umulhi(b1, 8388608u);
    float m2 = (float)__umulhi(b2, 8388608u);
    float m3 = (float)__umulhi(b3, 8388608u);
    fcnt += (float)(m0 < p23);
    fcnt += (float)(m1 < p23);
    fcnt += (float)(m2 < p23);
    fcnt += (float)(m3 < p23);
  }
  out[j] = (2.0f * fcnt - 36.0f) * (1.0f / 36.0f);
}

extern "C" void kernel_launch(void* const* d_in, const int* in_sizes, int n_in,
                              void* d_out, int out_size) {
  const float* inputs = (const float*)d_in[0];
  const float* weight = (const float*)d_in[1];
  const float* gamma  = (const float*)d_in[2];
  const float* beta   = (const float*)d_in[3];
  float* out = (float*)d_out;

  k_quant_input<<<(B_*C_*HWD*HWD + 255) / 256, 256>>>(inputs, B_*C_*HWD*HWD);
  k_qw<<<O_, 128>>>(weight);
  k_im2col<<<B_ * 32, 256>>>();
  dim3 gg(8, 4, S_ * B_);
  k_gemm<<<gg, 256>>>();
  k_stats<<<S_ * O_, 128>>>(gamma, beta);
  k_sample<<<BOL / 256, 256>>>(out);
}

// round 10
// speedup vs baseline: 1.1800x; 1.1800x over previous
#include <cuda_runtime.h>
#include <cstdint>
#include <math.h>

#define B_    32
#define C_    128
#define O_    256
#define HWD   32
#define L_    1024
#define CKK   1152
#define S_    9
#define SUBK  128
#define BOL   8388608       // B*O*L  (s-stride in y)
#define OLl   262144        // O*L    (b-stride in y)

// ---------------- device scratch ----------------
__device__ __align__(16) int8_t  g_qi[B_*C_*HWD*HWD];
__device__ __align__(16) int8_t  g_qw[O_*CKK];
__device__ __align__(16) int8_t  g_qa[(size_t)B_*L_*CKK];
__device__ __align__(16) short   g_y[(size_t)S_*BOL];
__device__ float g_A[S_*O_];   // inv_std*gamma/3
__device__ float g_Bc[S_*O_];  // beta - mean*inv_std*gamma

// ---------------- compile-time threefry keys ----------------
constexpr uint32_t crotl(uint32_t x, int r){ return (x << r) | (x >> (32 - r)); }
struct KP { uint32_t a, b; };
constexpr KP host_tf(uint32_t k0, uint32_t k1, uint32_t x0, uint32_t x1){
  uint32_t ks2 = k0 ^ k1 ^ 0x1BD11BDAu;
  x0 += k0; x1 += k1;
  const int RA[4] = {13,15,26,6};
  const int RB[4] = {17,29,16,24};
  const uint32_t ka[5] = {k1, ks2, k0, k1, ks2};
  const uint32_t kb[5] = {ks2, k0, k1, ks2, k0};
  for (int blk = 0; blk < 5; blk++){
    const int* R = (blk & 1) ? RB : RA;
    for (int i = 0; i < 4; i++){ x0 += x1; x1 = crotl(x1, R[i]); x1 ^= x0; }
    x0 += ka[blk]; x1 += kb[blk] + (uint32_t)(blk + 1);
  }
  return KP{x0, x1};
}
// fold_in(key(42), t) = threefry2x32(key=[0,42], data=[0,t])
constexpr KP KEY0 = host_tf(0u, 42u, 0u, 0u);
constexpr KP KEY1 = host_tf(0u, 42u, 0u, 1u);
constexpr KP KEY2 = host_tf(0u, 42u, 0u, 2u);
constexpr KP KEY3 = host_tf(0u, 42u, 0u, 3u);

// ---- R4-proven threefry config: plain rounds, only the three r=26 rotates as IMAD pair ----
#define TF_ROUND(r) { x0 += x1; x1 = __funnelshift_l(x1, x1, (r)); x1 ^= x0; }
#define TF_ROUND_M(r) { x0 += x1; \
  x1 = (x1 * (1u << (r))) + __umulhi(x1, 1u << (r)); x1 ^= x0; }

template<uint32_t K0, uint32_t K1>
__device__ __forceinline__ uint32_t tf_bits(uint32_t ctr){
  constexpr uint32_t KS2 = K0 ^ K1 ^ 0x1BD11BDAu;
  uint32_t x0 = K0;            // ctr_hi = 0
  uint32_t x1 = ctr + K1;
  TF_ROUND(13) TF_ROUND(15) TF_ROUND_M(26) TF_ROUND(6)
  x0 += K1;  x1 += KS2 + 1u;
  TF_ROUND(17) TF_ROUND(29) TF_ROUND(16) TF_ROUND(24)
  x0 += KS2; x1 += K0 + 2u;
  TF_ROUND(13) TF_ROUND(15) TF_ROUND_M(26) TF_ROUND(6)
  x0 += K0;  x1 += K1 + 3u;
  TF_ROUND(17) TF_ROUND(29) TF_ROUND(16) TF_ROUND(24)
  x0 += K1;  x1 += KS2 + 4u;
  TF_ROUND(13) TF_ROUND(15) TF_ROUND_M(26) TF_ROUND(6)
  x0 += KS2; x1 += K0 + 5u;
  return x0 ^ x1;              // partitionable: out = w0 ^ w1
}

// ---------------- k1: quantize input ----------------
__global__ void k_quant_input(const float* __restrict__ in, int n){
  int i = blockIdx.x * 256 + threadIdx.x;
  if (i < n){
    float v = fminf(fmaxf(in[i], -1.0f), 1.0f);
    g_qi[i] = (int8_t)__float2int_rn(v * 3.0f);
  }
}

// ---------------- k2: weight sign ----------------
__global__ void k_qw(const float* __restrict__ w){
  int o = blockIdx.x, t = threadIdx.x;
  const float* wr = w + (size_t)o * CKK;
  double s = 0.0;
  for (int i = t; i < CKK; i += 128) s += (double)wr[i];
  __shared__ double sh[128];
  sh[t] = s; __syncthreads();
  for (int d = 64; d; d >>= 1){ if (t < d) sh[t] += sh[t + d]; __syncthreads(); }
  float m = (float)(sh[0] / (double)CKK);
  for (int i = t; i < CKK; i += 128){
    float d = wr[i] - m;
    g_qw[(size_t)o * CKK + i] = (int8_t)((d > 0.0f) - (d < 0.0f));
  }
}

// ---------------- k3: im2col [b][l][ckk], ckk = c*9 + dy*3 + dx ----------------
__global__ void k_im2col(){
  int bid = blockIdx.x;
  int b = bid >> 5, y0 = bid & 31;
  int t = threadIdx.x;
  __shared__ int8_t sq[C_ * 3 * HWD];
  for (int i = t; i < C_ * 3 * HWD; i += 256){
    int c = i / 96, rr = (i % 96) >> 5, x = i & 31;
    int yy = y0 + rr - 1;
    sq[i] = (yy >= 0 && yy < HWD) ? g_qi[((size_t)(b * C_ + c) * HWD + yy) * HWD + x] : (int8_t)0;
  }
  __syncthreads();
  int8_t* dst = g_qa + (size_t)(b * L_ + y0 * HWD) * CKK;
  for (int idx = t; idx < HWD * CKK; idx += 256){
    int x0 = idx / CKK, ck = idx - x0 * CKK;
    int c = ck / 9, j = ck - c * 9;
    int dy = j / 3, dx = j - dy * 3;
    int xx = x0 + dx - 1;
    int8_t v = 0;
    if (xx >= 0 && xx < HWD) v = sq[(c * 3 + dy) * HWD + xx];
    dst[idx] = v;
  }
}

// ---------------- k4: per-subarray int8 GEMM (dp4a), 128l x 64o tile ----------------
__global__ void __launch_bounds__(256) k_gemm(){
  int l0 = blockIdx.x * 128, o0 = blockIdx.y * 64;
  int sb = blockIdx.z, s = sb >> 5, b = sb & 31;
  __shared__ __align__(16) int8_t sA[128][144];
  __shared__ __align__(16) int8_t sW[64][144];
  int t = threadIdx.x;
  const int8_t* gA = g_qa + (size_t)(b * L_ + l0) * CKK + s * SUBK;
  const int8_t* gW = g_qw + (size_t)o0 * CKK + s * SUBK;
  #pragma unroll
  for (int m = t; m < 1024; m += 256){
    int row = m >> 3, c16 = (m & 7) * 16;
    *(int4*)&sA[row][c16] = *(const int4*)(gA + (size_t)row * CKK + c16);
  }
  #pragma unroll
  for (int m = t; m < 512; m += 256){
    int row = m >> 3, c16 = (m & 7) * 16;
    *(int4*)&sW[row][c16] = *(const int4*)(gW + (size_t)row * CKK + c16);
  }
  __syncthreads();
  int tx = t & 15, ty = t >> 4;
  int acc[4][8] = {};
  #pragma unroll
  for (int kc = 0; kc < 8; kc++){
    int4 a4[8], w4[4];
    #pragma unroll
    for (int il = 0; il < 8; il++) a4[il] = *(const int4*)&sA[tx + 16 * il][kc * 16];
    #pragma unroll
    for (int io = 0; io < 4; io++) w4[io] = *(const int4*)&sW[ty + 16 * io][kc * 16];
    #pragma unroll
    for (int io = 0; io < 4; io++)
      #pragma unroll
      for (int il = 0; il < 8; il++){
        acc[io][il] = __dp4a(a4[il].x, w4[io].x, acc[io][il]);
        acc[io][il] = __dp4a(a4[il].y, w4[io].y, acc[io][il]);
        acc[io][il] = __dp4a(a4[il].z, w4[io].z, acc[io][il]);
        acc[io][il] = __dp4a(a4[il].w, w4[io].w, acc[io][il]);
      }
  }
  size_t base = (size_t)s * BOL + (size_t)b * OLl;
  #pragma unroll
  for (int io = 0; io < 4; io++)
    #pragma unroll
    for (int il = 0; il < 8; il++)
      g_y[base + (size_t)(o0 + ty + 16 * io) * 1024 + (l0 + tx + 16 * il)] = (short)acc[io][il];
}

// ---------------- k5: BN stats per (s,o) ----------------
__global__ void k_stats(const float* __restrict__ gamma, const float* __restrict__ beta){
  int so = blockIdx.x;
  int s = so >> 8, o = so & 255;
  int t = threadIdx.x;                  // 128
  const int4* base = (const int4*)(g_y + (size_t)s * BOL + (size_t)o * 1024);
  int sy = 0; unsigned int sy2 = 0;
  #pragma unroll 4
  for (int b = 0; b < B_; b++){
    int4 v = base[(size_t)b * (OLl / 8) + t];
    short vv[8]; *(int4*)vv = v;
    #pragma unroll
    for (int q = 0; q < 8; q++){
      int x = vv[q];
      sy += x; sy2 += (unsigned int)(x * x);
    }
  }
  for (int d = 16; d; d >>= 1){
    sy  += __shfl_down_sync(0xffffffffu, sy, d);
    sy2 += __shfl_down_sync(0xffffffffu, sy2, d);
  }
  __shared__ int ssy[4]; __shared__ unsigned int ssy2[4];
  if ((t & 31) == 0){ ssy[t >> 5] = sy; ssy2[t >> 5] = sy2; }
  __syncthreads();
  if (t == 0){
    long long S1 = 0; unsigned long long S2 = 0;
    #pragma unroll
    for (int w = 0; w < 4; w++){ S1 += ssy[w]; S2 += ssy2[w]; }
    const double N = 32768.0;
    double mean = (double)S1 / (3.0 * N);
    double e2   = (double)S2 / (9.0 * N);
    double var  = e2 - mean * mean;
    double inv  = (double)gamma[o] / sqrt(var + 1e-5);
    g_A[so]  = (float)(inv / 3.0);
    g_Bc[so] = (float)((double)beta[o] - mean * inv);
  }
}

// ---------------- k6: sampling — R4 arithmetic, preloaded loads, s-unroll x3 ----------------
// compare trick: u < p  <=>  (float)(bits>>9) < p*2^23   (all quantities exact in f32)
__global__ void __launch_bounds__(256) k_sample(float* __restrict__ out){
  uint32_t j = blockIdx.x * 256 + threadIdx.x;    // flat (b,o,l)
  int o = (j >> 10) & 255;

  // batched y loads: MLP=9, no per-iteration exposed DRAM latency
  short yv[S_];
  #pragma unroll
  for (int s = 0; s < S_; s++) yv[s] = __ldg(&g_y[(size_t)s * BOL + j]);

  // all 9 thresholds up front (identical arithmetic to R4)
  float p23[S_];
  #pragma unroll
  for (int s = 0; s < S_; s++){
    float A  = __ldg(&g_A[s * 256 + o]);
    float Bc = __ldg(&g_Bc[s * 256 + o]);
    float zf = fmaf((float)yv[s], A, Bc);
    zf = fminf(fmaxf(zf, -1.0f), 1.0f);
    float p = fminf(fmaxf((zf + 1.0f) * 0.5f, 0.0f), 1.0f);
    p23[s] = p * 8388608.0f;                      // exact (power-of-2 scale)
  }

  float fcnt = 0.0f;
  #pragma unroll 3
  for (int s = 0; s < S_; s++){                   // 3 s-iters in flight -> 12 chains
    uint32_t idx = (uint32_t)s * BOL + j;
    uint32_t b0 = tf_bits<KEY0.a, KEY0.b>(idx);
    uint32_t b1 = tf_bits<KEY1.a, KEY1.b>(idx);
    uint32_t b2 = tf_bits<KEY2.a, KEY2.b>(idx);
    uint32_t b3 = tf_bits<KEY3.a, KEY3.b>(idx);
    float m0 = (float)__umulhi(b0, 8388608u);     // == b0 >> 9, off the alu pipe
    float m1 = (float)__umulhi(b1, 8388608u);
    float m2 = (float)__umulhi(b2, 8388608u);
    float m3 = (float)__umulhi(b3, 8388608u);
    float ps = p23[s];
    fcnt += (float)(m0 < ps);
    fcnt += (float)(m1 < ps);
    fcnt += (float)(m2 < ps);
    fcnt += (float)(m3 < ps);
  }
  out[j] = (2.0f * fcnt - 36.0f) * (1.0f / 36.0f);
}

extern "C" void kernel_launch(void* const* d_in, const int* in_sizes, int n_in,
                              void* d_out, int out_size) {
  const float* inputs = (const float*)d_in[0];
  const float* weight = (const float*)d_in[1];
  const float* gamma  = (const float*)d_in[2];
  const float* beta   = (const float*)d_in[3];
  float* out = (float*)d_out;

  k_quant_input<<<(B_*C_*HWD*HWD + 255) / 256, 256>>>(inputs, B_*C_*HWD*HWD);
  k_qw<<<O_, 128>>>(weight);
  k_im2col<<<B_ * 32, 256>>>();
  dim3 gg(8, 4, S_ * B_);
  k_gemm<<<gg, 256>>>();
  k_stats<<<S_ * O_, 128>>>(gamma, beta);
  k_sample<<<BOL / 256, 256>>>(out);
}

// round 11
// speedup vs baseline: 1.1906x; 1.0091x over previous
#include <cuda_runtime.h>
#include <cstdint>
#include <math.h>

#define B_    32
#define C_    128
#define O_    256
#define HWD   32
#define L_    1024
#define CKK   1152
#define S_    9
#define SUBK  128
#define BOL   8388608       // B*O*L  (s-stride in y)
#define OLl   262144        // O*L    (b-stride in y)

// ---------------- device scratch ----------------
__device__ __align__(16) int8_t  g_qi[B_*C_*HWD*HWD];
__device__ __align__(16) int8_t  g_qw[O_*CKK];
__device__ __align__(16) int8_t  g_qa[(size_t)B_*L_*CKK];
__device__ __align__(16) short   g_y[(size_t)S_*BOL];
__device__ int                g_S1[S_*O_];       // exact integer  sum y_int
__device__ unsigned long long g_S2[S_*O_];       // exact integer  sum y_int^2
__device__ float g_A[S_*O_];   // inv_std*gamma/3
__device__ float g_Bc[S_*O_];  // beta - mean*inv_std*gamma

// ---------------- compile-time threefry keys ----------------
constexpr uint32_t crotl(uint32_t x, int r){ return (x << r) | (x >> (32 - r)); }
struct KP { uint32_t a, b; };
constexpr KP host_tf(uint32_t k0, uint32_t k1, uint32_t x0, uint32_t x1){
  uint32_t ks2 = k0 ^ k1 ^ 0x1BD11BDAu;
  x0 += k0; x1 += k1;
  const int RA[4] = {13,15,26,6};
  const int RB[4] = {17,29,16,24};
  const uint32_t ka[5] = {k1, ks2, k0, k1, ks2};
  const uint32_t kb[5] = {ks2, k0, k1, ks2, k0};
  for (int blk = 0; blk < 5; blk++){
    const int* R = (blk & 1) ? RB : RA;
    for (int i = 0; i < 4; i++){ x0 += x1; x1 = crotl(x1, R[i]); x1 ^= x0; }
    x0 += ka[blk]; x1 += kb[blk] + (uint32_t)(blk + 1);
  }
  return KP{x0, x1};
}
// fold_in(key(42), t) = threefry2x32(key=[0,42], data=[0,t])
constexpr KP KEY0 = host_tf(0u, 42u, 0u, 0u);
constexpr KP KEY1 = host_tf(0u, 42u, 0u, 1u);
constexpr KP KEY2 = host_tf(0u, 42u, 0u, 2u);
constexpr KP KEY3 = host_tf(0u, 42u, 0u, 3u);

// ---- R4/R10-proven threefry config ----
#define TF_ROUND(r) { x0 += x1; x1 = __funnelshift_l(x1, x1, (r)); x1 ^= x0; }
#define TF_ROUND_M(r) { x0 += x1; \
  x1 = (x1 * (1u << (r))) + __umulhi(x1, 1u << (r)); x1 ^= x0; }

template<uint32_t K0, uint32_t K1>
__device__ __forceinline__ uint32_t tf_bits(uint32_t ctr){
  constexpr uint32_t KS2 = K0 ^ K1 ^ 0x1BD11BDAu;
  uint32_t x0 = K0;            // ctr_hi = 0
  uint32_t x1 = ctr + K1;
  TF_ROUND(13) TF_ROUND(15) TF_ROUND_M(26) TF_ROUND(6)
  x0 += K1;  x1 += KS2 + 1u;
  TF_ROUND(17) TF_ROUND(29) TF_ROUND(16) TF_ROUND(24)
  x0 += KS2; x1 += K0 + 2u;
  TF_ROUND(13) TF_ROUND(15) TF_ROUND_M(26) TF_ROUND(6)
  x0 += K0;  x1 += K1 + 3u;
  TF_ROUND(17) TF_ROUND(29) TF_ROUND(16) TF_ROUND(24)
  x0 += K1;  x1 += KS2 + 4u;
  TF_ROUND(13) TF_ROUND(15) TF_ROUND_M(26) TF_ROUND(6)
  x0 += KS2; x1 += K0 + 5u;
  return x0 ^ x1;              // partitionable: out = w0 ^ w1
}

// ---------------- k0: zero the stat accumulators (graph-replay safe) ----------------
__global__ void k_zero_stats(){
  int i = blockIdx.x * 256 + threadIdx.x;
  if (i < S_*O_){ g_S1[i] = 0; g_S2[i] = 0ull; }
}

// ---------------- k1: quantize input ----------------
__global__ void k_quant_input(const float* __restrict__ in, int n){
  int i = blockIdx.x * 256 + threadIdx.x;
  if (i < n){
    float v = fminf(fmaxf(in[i], -1.0f), 1.0f);
    g_qi[i] = (int8_t)__float2int_rn(v * 3.0f);
  }
}

// ---------------- k2: weight sign ----------------
__global__ void k_qw(const float* __restrict__ w){
  int o = blockIdx.x, t = threadIdx.x;
  const float* wr = w + (size_t)o * CKK;
  double s = 0.0;
  for (int i = t; i < CKK; i += 128) s += (double)wr[i];
  __shared__ double sh[128];
  sh[t] = s; __syncthreads();
  for (int d = 64; d; d >>= 1){ if (t < d) sh[t] += sh[t + d]; __syncthreads(); }
  float m = (float)(sh[0] / (double)CKK);
  for (int i = t; i < CKK; i += 128){
    float d = wr[i] - m;
    g_qw[(size_t)o * CKK + i] = (int8_t)((d > 0.0f) - (d < 0.0f));
  }
}

// ---------------- k3: im2col [b][l][ckk], ckk = c*9 + dy*3 + dx ----------------
__global__ void k_im2col(){
  int bid = blockIdx.x;
  int b = bid >> 5, y0 = bid & 31;
  int t = threadIdx.x;
  __shared__ int8_t sq[C_ * 3 * HWD];
  for (int i = t; i < C_ * 3 * HWD; i += 256){
    int c = i / 96, rr = (i % 96) >> 5, x = i & 31;
    int yy = y0 + rr - 1;
    sq[i] = (yy >= 0 && yy < HWD) ? g_qi[((size_t)(b * C_ + c) * HWD + yy) * HWD + x] : (int8_t)0;
  }
  __syncthreads();
  int8_t* dst = g_qa + (size_t)(b * L_ + y0 * HWD) * CKK;
  for (int idx = t; idx < HWD * CKK; idx += 256){
    int x0 = idx / CKK, ck = idx - x0 * CKK;
    int c = ck / 9, j = ck - c * 9;
    int dy = j / 3, dx = j - dy * 3;
    int xx = x0 + dx - 1;
    int8_t v = 0;
    if (xx >= 0 && xx < HWD) v = sq[(c * 3 + dy) * HWD + xx];
    dst[idx] = v;
  }
}

// ---------------- k4: int8 GEMM (dp4a) + fused BN-stat accumulation ----------------
__global__ void __launch_bounds__(256) k_gemm(){
  int l0 = blockIdx.x * 128, o0 = blockIdx.y * 64;
  int sb = blockIdx.z, s = sb >> 5, b = sb & 31;
  __shared__ __align__(16) int8_t sA[128][144];
  __shared__ __align__(16) int8_t sW[64][144];
  int t = threadIdx.x;
  const int8_t* gA = g_qa + (size_t)(b * L_ + l0) * CKK + s * SUBK;
  const int8_t* gW = g_qw + (size_t)o0 * CKK + s * SUBK;
  #pragma unroll
  for (int m = t; m < 1024; m += 256){
    int row = m >> 3, c16 = (m & 7) * 16;
    *(int4*)&sA[row][c16] = *(const int4*)(gA + (size_t)row * CKK + c16);
  }
  #pragma unroll
  for (int m = t; m < 512; m += 256){
    int row = m >> 3, c16 = (m & 7) * 16;
    *(int4*)&sW[row][c16] = *(const int4*)(gW + (size_t)row * CKK + c16);
  }
  __syncthreads();
  int tx = t & 15, ty = t >> 4;
  int acc[4][8] = {};
  #pragma unroll
  for (int kc = 0; kc < 8; kc++){
    int4 a4[8], w4[4];
    #pragma unroll
    for (int il = 0; il < 8; il++) a4[il] = *(const int4*)&sA[tx + 16 * il][kc * 16];
    #pragma unroll
    for (int io = 0; io < 4; io++) w4[io] = *(const int4*)&sW[ty + 16 * io][kc * 16];
    #pragma unroll
    for (int io = 0; io < 4; io++)
      #pragma unroll
      for (int il = 0; il < 8; il++){
        acc[io][il] = __dp4a(a4[il].x, w4[io].x, acc[io][il]);
        acc[io][il] = __dp4a(a4[il].y, w4[io].y, acc[io][il]);
        acc[io][il] = __dp4a(a4[il].z, w4[io].z, acc[io][il]);
        acc[io][il] = __dp4a(a4[il].w, w4[io].w, acc[io][il]);
      }
  }
  size_t base = (size_t)s * BOL + (size_t)b * OLl;
  #pragma unroll
  for (int io = 0; io < 4; io++)
    #pragma unroll
    for (int il = 0; il < 8; il++)
      g_y[base + (size_t)(o0 + ty + 16 * io) * 1024 + (l0 + tx + 16 * il)] = (short)acc[io][il];

  // ---- fused BN statistics: exact integer sums per (s, o-row) ----
  // Each o-row (o0+ty+16*io) is held by the 16 tx lanes (8 l-values each).
  #pragma unroll
  for (int io = 0; io < 4; io++){
    int s1 = 0, s2 = 0;                      // |s1|<=3072, s2<=1.2M per thread
    #pragma unroll
    for (int il = 0; il < 8; il++){
      int v = acc[io][il];
      s1 += v; s2 += v * v;                  // s2 over 16 lanes <= 18.9M: int32 ok
    }
    #pragma unroll
    for (int d = 8; d; d >>= 1){             // reduce across the 16-lane tx group
      s1 += __shfl_down_sync(0xffffffffu, s1, d, 16);
      s2 += __shfl_down_sync(0xffffffffu, s2, d, 16);
    }
    if (tx == 0){
      int so = s * 256 + (o0 + ty + 16 * io);
      atomicAdd(&g_S1[so], s1);
      atomicAdd(&g_S2[so], (unsigned long long)(unsigned int)s2);
    }
  }
}

// ---------------- k5: finalize BN coefficients (same math as before, same integers) ----
__global__ void k_finalize(const float* __restrict__ gamma, const float* __restrict__ beta){
  int so = blockIdx.x * 256 + threadIdx.x;
  if (so >= S_*O_) return;
  int o = so & 255;
  const double N = 32768.0;
  double mean = (double)g_S1[so] / (3.0 * N);
  double e2   = (double)g_S2[so] / (9.0 * N);
  double var  = e2 - mean * mean;
  double inv  = (double)gamma[o] / sqrt(var + 1e-5);
  g_A[so]  = (float)(inv / 3.0);
  g_Bc[so] = (float)((double)beta[o] - mean * inv);
}

// ---------------- k6: sampling (R10-proven) ----------------
// compare trick: u < p  <=>  (float)(bits>>9) < p*2^23   (all quantities exact in f32)
__global__ void __launch_bounds__(256) k_sample(float* __restrict__ out){
  uint32_t j = blockIdx.x * 256 + threadIdx.x;    // flat (b,o,l)
  int o = (j >> 10) & 255;

  short yv[S_];
  #pragma unroll
  for (int s = 0; s < S_; s++) yv[s] = __ldg(&g_y[(size_t)s * BOL + j]);

  float p23[S_];
  #pragma unroll
  for (int s = 0; s < S_; s++){
    float A  = __ldg(&g_A[s * 256 + o]);
    float Bc = __ldg(&g_Bc[s * 256 + o]);
    float zf = fmaf((float)yv[s], A, Bc);
    zf = fminf(fmaxf(zf, -1.0f), 1.0f);
    float p = fminf(fmaxf((zf + 1.0f) * 0.5f, 0.0f), 1.0f);
    p23[s] = p * 8388608.0f;                      // exact (power-of-2 scale)
  }

  float fcnt = 0.0f;
  #pragma unroll 3
  for (int s = 0; s < S_; s++){
    uint32_t idx = (uint32_t)s * BOL + j;
    uint32_t b0 = tf_bits<KEY0.a, KEY0.b>(idx);
    uint32_t b1 = tf_bits<KEY1.a, KEY1.b>(idx);
    uint32_t b2 = tf_bits<KEY2.a, KEY2.b>(idx);
    uint32_t b3 = tf_bits<KEY3.a, KEY3.b>(idx);
    float m0 = (float)__umulhi(b0, 8388608u);     // == b0 >> 9, off the alu pipe
    float m1 = (float)__umulhi(b1, 8388608u);
    float m2 = (float)__umulhi(b2, 8388608u);
    float m3 = (float)__umulhi(b3, 8388608u);
    float ps = p23[s];
    fcnt += (float)(m0 < ps);
    fcnt += (float)(m1 < ps);
    fcnt += (float)(m2 < ps);
    fcnt += (float)(m3 < ps);
  }
  out[j] = (2.0f * fcnt - 36.0f) * (1.0f / 36.0f);
}

extern "C" void kernel_launch(void* const* d_in, const int* in_sizes, int n_in,
                              void* d_out, int out_size) {
  const float* inputs = (const float*)d_in[0];
  const float* weight = (const float*)d_in[1];
  const float* gamma  = (const float*)d_in[2];
  const float* beta   = (const float*)d_in[3];
  float* out = (float*)d_out;

  k_zero_stats<<<(S_*O_ + 255) / 256, 256>>>();
  k_quant_input<<<(B_*C_*HWD*HWD + 255) / 256, 256>>>(inputs, B_*C_*HWD*HWD);
  k_qw<<<O_, 128>>>(weight);
  k_im2col<<<B_ * 32, 256>>>();
  dim3 gg(8, 4, S_ * B_);
  k_gemm<<<gg, 256>>>();
  k_finalize<<<(S_*O_ + 255) / 256, 256>>>(gamma, beta);
  k_sample<<<BOL / 256, 256>>>(out);
}

// round 14
// speedup vs baseline: 1.3942x; 1.1709x over previous
#include <cuda_runtime.h>
#include <cstdint>
#include <math.h>

#define B_    32
#define C_    128
#define O_    256
#define HWD   32
#define L_    1024
#define CKK   1152
#define S_    9
#define SUBK  128
#define BOL   8388608       // B*O*L  (s-stride in y)
#define OLl   262144        // O*L    (b-stride in y)

// ---------------- device scratch ----------------
__device__ __align__(16) int8_t  g_qi[B_*C_*HWD*HWD];
__device__ __align__(16) int8_t  g_qw[O_*CKK];
__device__ __align__(16) int8_t  g_qa[(size_t)B_*L_*CKK];
__device__ __align__(16) short   g_y[(size_t)S_*BOL];
__device__ int                g_S1[S_*O_];       // exact integer sum y_int
__device__ unsigned long long g_S2[S_*O_];       // exact integer sum y_int^2
__device__ float g_A[S_*O_];   // inv_std*gamma/3
__device__ float g_Bc[S_*O_];  // beta - mean*inv_std*gamma

// ---------------- compile-time threefry keys ----------------
constexpr uint32_t crotl(uint32_t x, int r){ return (x << r) | (x >> (32 - r)); }
struct KP { uint32_t a, b; };
constexpr KP host_tf(uint32_t k0, uint32_t k1, uint32_t x0, uint32_t x1){
  uint32_t ks2 = k0 ^ k1 ^ 0x1BD11BDAu;
  x0 += k0; x1 += k1;
  const int RA[4] = {13,15,26,6};
  const int RB[4] = {17,29,16,24};
  const uint32_t ka[5] = {k1, ks2, k0, k1, ks2};
  const uint32_t kb[5] = {ks2, k0, k1, ks2, k0};
  for (int blk = 0; blk < 5; blk++){
    const int* R = (blk & 1) ? RB : RA;
    for (int i = 0; i < 4; i++){ x0 += x1; x1 = crotl(x1, R[i]); x1 ^= x0; }
    x0 += ka[blk]; x1 += kb[blk] + (uint32_t)(blk + 1);
  }
  return KP{x0, x1};
}
// fold_in(key(42), t) = threefry2x32(key=[0,42], data=[0,t])
constexpr KP KEY0 = host_tf(0u, 42u, 0u, 0u);
constexpr KP KEY1 = host_tf(0u, 42u, 0u, 1u);
constexpr KP KEY2 = host_tf(0u, 42u, 0u, 2u);
constexpr KP KEY3 = host_tf(0u, 42u, 0u, 3u);

// ---- R4/R10-proven threefry config ----
#define TF_ROUND(r) { x0 += x1; x1 = __funnelshift_l(x1, x1, (r)); x1 ^= x0; }
#define TF_ROUND_M(r) { x0 += x1; \
  x1 = (x1 * (1u << (r))) + __umulhi(x1, 1u << (r)); x1 ^= x0; }

template<uint32_t K0, uint32_t K1>
__device__ __forceinline__ uint32_t tf_bits(uint32_t ctr){
  constexpr uint32_t KS2 = K0 ^ K1 ^ 0x1BD11BDAu;
  uint32_t x0 = K0;            // ctr_hi = 0
  uint32_t x1 = ctr + K1;
  TF_ROUND(13) TF_ROUND(15) TF_ROUND_M(26) TF_ROUND(6)
  x0 += K1;  x1 += KS2 + 1u;
  TF_ROUND(17) TF_ROUND(29) TF_ROUND(16) TF_ROUND(24)
  x0 += KS2; x1 += K0 + 2u;
  TF_ROUND(13) TF_ROUND(15) TF_ROUND_M(26) TF_ROUND(6)
  x0 += K0;  x1 += K1 + 3u;
  TF_ROUND(17) TF_ROUND(29) TF_ROUND(16) TF_ROUND(24)
  x0 += K1;  x1 += KS2 + 4u;
  TF_ROUND(13) TF_ROUND(15) TF_ROUND_M(26) TF_ROUND(6)
  x0 += KS2; x1 += K0 + 5u;
  return x0 ^ x1;              // partitionable: out = w0 ^ w1
}

// ---------------- k0: zero the stat accumulators (graph-replay safe) ----------------
__global__ void k_zero_stats(){
  int i = blockIdx.x * 256 + threadIdx.x;
  if (i < S_*O_){ g_S1[i] = 0; g_S2[i] = 0ull; }
}

// ---------------- k1: quantize input ----------------
__global__ void k_quant_input(const float* __restrict__ in, int n){
  int i = blockIdx.x * 256 + threadIdx.x;
  if (i < n){
    float v = fminf(fmaxf(in[i], -1.0f), 1.0f);
    g_qi[i] = (int8_t)__float2int_rn(v * 3.0f);
  }
}

// ---------------- k2: weight sign ----------------
__global__ void k_qw(const float* __restrict__ w){
  int o = blockIdx.x, t = threadIdx.x;
  const float* wr = w + (size_t)o * CKK;
  double s = 0.0;
  for (int i = t; i < CKK; i += 128) s += (double)wr[i];
  __shared__ double sh[128];
  sh[t] = s; __syncthreads();
  for (int d = 64; d; d >>= 1){ if (t < d) sh[t] += sh[t + d]; __syncthreads(); }
  float m = (float)(sh[0] / (double)CKK);
  for (int i = t; i < CKK; i += 128){
    float d = wr[i] - m;
    g_qw[(size_t)o * CKK + i] = (int8_t)((d > 0.0f) - (d < 0.0f));
  }
}

// ---------------- k3: im2col [b][l][ckk], ckk = c*9 + dy*3 + dx ----------------
__global__ void k_im2col(){
  int bid = blockIdx.x;
  int b = bid >> 5, y0 = bid & 31;
  int t = threadIdx.x;
  __shared__ int8_t sq[C_ * 3 * HWD];
  for (int i = t; i < C_ * 3 * HWD; i += 256){
    int c = i / 96, rr = (i % 96) >> 5, x = i & 31;
    int yy = y0 + rr - 1;
    sq[i] = (yy >= 0 && yy < HWD) ? g_qi[((size_t)(b * C_ + c) * HWD + yy) * HWD + x] : (int8_t)0;
  }
  __syncthreads();
  int8_t* dst = g_qa + (size_t)(b * L_ + y0 * HWD) * CKK;
  for (int idx = t; idx < HWD * CKK; idx += 256){
    int x0 = idx / CKK, ck = idx - x0 * CKK;
    int c = ck / 9, j = ck - c * 9;
    int dy = j / 3, dx = j - dy * 3;
    int xx = x0 + dx - 1;
    int8_t v = 0;
    if (xx >= 0 && xx < HWD) v = sq[(c * 3 + dy) * HWD + xx];
    dst[idx] = v;
  }
}

// ---------------- k4: int8 GEMM (dp4a) + fused BN-stat accumulation ----------------
__global__ void __launch_bounds__(256) k_gemm(){
  int l0 = blockIdx.x * 128, o0 = blockIdx.y * 64;
  int sb = blockIdx.z, s = sb >> 5, b = sb & 31;
  __shared__ __align__(16) int8_t sA[128][144];
  __shared__ __align__(16) int8_t sW[64][144];
  int t = threadIdx.x;
  const int8_t* gA = g_qa + (size_t)(b * L_ + l0) * CKK + s * SUBK;
  const int8_t* gW = g_qw + (size_t)o0 * CKK + s * SUBK;
  #pragma unroll
  for (int m = t; m < 1024; m += 256){
    int row = m >> 3, c16 = (m & 7) * 16;
    *(int4*)&sA[row][c16] = *(const int4*)(gA + (size_t)row * CKK + c16);
  }
  #pragma unroll
  for (int m = t; m < 512; m += 256){
    int row = m >> 3, c16 = (m & 7) * 16;
    *(int4*)&sW[row][c16] = *(const int4*)(gW + (size_t)row * CKK + c16);
  }
  __syncthreads();
  int tx = t & 15, ty = t >> 4;
  int acc[4][8] = {};
  #pragma unroll
  for (int kc = 0; kc < 8; kc++){
    int4 a4[8], w4[4];
    #pragma unroll
    for (int il = 0; il < 8; il++) a4[il] = *(const int4*)&sA[tx + 16 * il][kc * 16];
    #pragma unroll
    for (int io = 0; io < 4; io++) w4[io] = *(const int4*)&sW[ty + 16 * io][kc * 16];
    #pragma unroll
    for (int io = 0; io < 4; io++)
      #pragma unroll
      for (int il = 0; il < 8; il++){
        acc[io][il] = __dp4a(a4[il].x, w4[io].x, acc[io][il]);
        acc[io][il] = __dp4a(a4[il].y, w4[io].y, acc[io][il]);
        acc[io][il] = __dp4a(a4[il].z, w4[io].z, acc[io][il]);
        acc[io][il] = __dp4a(a4[il].w, w4[io].w, acc[io][il]);
      }
  }
  size_t base = (size_t)s * BOL + (size_t)b * OLl;
  #pragma unroll
  for (int io = 0; io < 4; io++)
    #pragma unroll
    for (int il = 0; il < 8; il++)
      g_y[base + (size_t)(o0 + ty + 16 * io) * 1024 + (l0 + tx + 16 * il)] = (short)acc[io][il];

  // fused BN statistics: exact integer sums per (s, o-row)
  #pragma unroll
  for (int io = 0; io < 4; io++){
    int s1 = 0, s2 = 0;
    #pragma unroll
    for (int il = 0; il < 8; il++){
      int v = acc[io][il];
      s1 += v; s2 += v * v;
    }
    #pragma unroll
    for (int d = 8; d; d >>= 1){
      s1 += __shfl_down_sync(0xffffffffu, s1, d, 16);
      s2 += __shfl_down_sync(0xffffffffu, s2, d, 16);
    }
    if (tx == 0){
      int so = s * 256 + (o0 + ty + 16 * io);
      atomicAdd(&g_S1[so], s1);
      atomicAdd(&g_S2[so], (unsigned long long)(unsigned int)s2);
    }
  }
}

// ---------------- k5: finalize BN coefficients ----------------
__global__ void k_finalize(const float* __restrict__ gamma, const float* __restrict__ beta){
  int so = blockIdx.x * 256 + threadIdx.x;
  if (so >= S_*O_) return;
  int o = so & 255;
  const double N = 32768.0;
  double mean = (double)g_S1[so] / (3.0 * N);
  double e2   = (double)g_S2[so] / (9.0 * N);
  double var  = e2 - mean * mean;
  double inv  = (double)gamma[o] / sqrt(var + 1e-5);
  g_A[so]  = (float)(inv / 3.0);
  g_Bc[so] = (float)((double)beta[o] - mean * inv);
}

// ---------------- k6: sampling with intra-warp compaction of non-deterministic draws ----
// u < p  <=>  (float)(bits>>9) < p*2^23  (exact). p23==2^23 -> cnt=4 always; p23==0 -> 0.
__global__ void __launch_bounds__(256) k_sample(float* __restrict__ out){
  int tid = threadIdx.x;
  int wid = tid >> 5, lane = tid & 31;
  uint32_t j = blockIdx.x * 256 + tid;            // flat (b,o,l)
  uint32_t jw = j - lane;                         // warp-base j
  int o = (j >> 10) & 255;

  __shared__ float          sp23[8][S_][32];      // per-warp thresholds
  __shared__ unsigned short slist[8][S_ * 32];    // packed (s*32+lane) entries
  __shared__ int            scnt[8][32];          // per-source-lane count

  scnt[wid][lane] = 0;

  // thresholds (identical arithmetic to R4/R10)
  short yv[S_];
  #pragma unroll
  for (int s = 0; s < S_; s++) yv[s] = __ldg(&g_y[(size_t)s * BOL + j]);

  int nfull = 0, nlist = 0;
  #pragma unroll
  for (int s = 0; s < S_; s++){
    float A  = __ldg(&g_A[s * 256 + o]);
    float Bc = __ldg(&g_Bc[s * 256 + o]);
    float zf = fmaf((float)yv[s], A, Bc);
    zf = fminf(fmaxf(zf, -1.0f), 1.0f);
    float p = fminf(fmaxf((zf + 1.0f) * 0.5f, 0.0f), 1.0f);
    float ps = p * 8388608.0f;                    // exact
    sp23[wid][s][lane] = ps;
    bool full = (ps == 8388608.0f);
    bool zero = (ps == 0.0f);
    nfull += full;
    unsigned m = __ballot_sync(0xffffffffu, !full && !zero);
    if (!full && !zero)
      slist[wid][nlist + __popc(m & ((1u << lane) - 1u))] =
          (unsigned short)(s * 32 + lane);
    nlist += __popc(m);
  }
  __syncwarp();

  // dense hashing over the compacted worklist
  for (int e = lane; e < nlist; e += 32){
    int ent = slist[wid][e];
    int es = ent >> 5, el = ent & 31;
    float ps = sp23[wid][es][el];
    uint32_t idx = (uint32_t)es * BOL + jw + (uint32_t)el;
    uint32_t b0 = tf_bits<KEY0.a, KEY0.b>(idx);
    uint32_t b1 = tf_bits<KEY1.a, KEY1.b>(idx);
    uint32_t b2 = tf_bits<KEY2.a, KEY2.b>(idx);
    uint32_t b3 = tf_bits<KEY3.a, KEY3.b>(idx);
    int c = ((float)__umulhi(b0, 8388608u) < ps)
          + ((float)__umulhi(b1, 8388608u) < ps)
          + ((float)__umulhi(b2, 8388608u) < ps)
          + ((float)__umulhi(b3, 8388608u) < ps);
    atomicAdd(&scnt[wid][el], c);
  }
  __syncwarp();

  int total = 4 * nfull + scnt[wid][lane];
  out[j] = (2.0f * (float)total - 36.0f) * (1.0f / 36.0f);
}

extern "C" void kernel_launch(void* const* d_in, const int* in_sizes, int n_in,
                              void* d_out, int out_size) {
  const float* inputs = (const float*)d_in[0];
  const float* weight = (const float*)d_in[1];
  const float* gamma  = (const float*)d_in[2];
  const float* beta   = (const float*)d_in[3];
  float* out = (float*)d_out;

  k_zero_stats<<<(S_*O_ + 255) / 256, 256>>>();
  k_quant_input<<<(B_*C_*HWD*HWD + 255) / 256, 256>>>(inputs, B_*C_*HWD*HWD);
  k_qw<<<O_, 128>>>(weight);
  k_im2col<<<B_ * 32, 256>>>();
  dim3 gg(8, 4, S_ * B_);
  k_gemm<<<gg, 256>>>();
  k_finalize<<<(S_*O_ + 255) / 256, 256>>>(gamma, beta);
  k_sample<<<BOL / 256, 256>>>(out);
}